// round 6
// baseline (speedup 1.0000x reference)
#include <cuda_runtime.h>

#define ROWS 4096
#define COLS 8192
#define THREADS 512
#define NWARPS (THREADS / 32)          // 16
#define VPT (COLS / (THREADS * 4))     // 4 float4 per thread = 16 floats

__device__ __forceinline__ float warp_sum(float v) {
#pragma unroll
    for (int off = 16; off; off >>= 1)
        v += __shfl_xor_sync(0xffffffffu, v, off);
    return v;
}

__device__ __forceinline__ float warp_sum16(float v) {   // reduce 16 lanes' values
#pragma unroll
    for (int off = 8; off; off >>= 1)
        v += __shfl_xor_sync(0xffffffffu, v, off);
    return v;
}

__global__ void __launch_bounds__(THREADS, 3)
sparsemax_kernel(const float* __restrict__ x, float* __restrict__ out) {
    const int row  = blockIdx.x;
    const int t    = threadIdx.x;
    const int warp = t >> 5;
    const int lane = t & 31;

    const float4* __restrict__ x4 = reinterpret_cast<const float4*>(x + (size_t)row * COLS);
    float4*       __restrict__ o4 = reinterpret_cast<float4*>(out + (size_t)row * COLS);

    // Front-batched coalesced streaming loads (input is never re-read).
    float4 v[VPT];
#pragma unroll
    for (int i = 0; i < VPT; i++) v[i] = __ldcs(&x4[t + i * THREADS]);

    __shared__ float s_sum[2][NWARPS];
    __shared__ float s_cnt[2][NWARPS];

    // Per-thread max for pruning: once thread_max <= tau, this thread can
    // never contribute again (condition v > tau is recomputed exactly).
    float thread_max = v[0].x;
#pragma unroll
    for (int i = 0; i < VPT; i++) {
        thread_max = fmaxf(thread_max, fmaxf(fmaxf(v[i].x, v[i].y), fmaxf(v[i].z, v[i].w)));
    }

    const float NEG_INF = __int_as_float(0xff800000);
    float tau = NEG_INF;          // iter 0: all elements pass -> tau1 = (sum-1)/N
    bool alive = true;

    // Newton on g(tau) = sum(relu(x - tau)) - 1 : tau <- (sum_{x>tau} x - 1)/count.
    // tau0 left of the root on convex decreasing g => monotone, finite convergence
    // to the exact sparsemax threshold (same support set as the sort-based ref).
#pragma unroll 1
    for (int iter = 0; iter < 24; iter++) {
        float ps = 0.f, pc = 0.f;
        if (alive) {
#pragma unroll
            for (int i = 0; i < VPT; i++) {
                if (v[i].x > tau) { ps += v[i].x; pc += 1.f; }
                if (v[i].y > tau) { ps += v[i].y; pc += 1.f; }
                if (v[i].z > tau) { ps += v[i].z; pc += 1.f; }
                if (v[i].w > tau) { ps += v[i].w; pc += 1.f; }
            }
        }
        // Two independent shuffle chains pipeline against each other.
        ps = warp_sum(ps);
        pc = warp_sum(pc);

        const int buf = iter & 1;   // double buffer -> single barrier per iteration
        if (lane == 0) { s_sum[buf][warp] = ps; s_cnt[buf][warp] = pc; }
        __syncthreads();

        // Every warp redundantly reduces the 16 partials -> identical tau in
        // all warps, no second barrier, no serial single-thread section.
        float S = (lane < NWARPS) ? s_sum[buf][lane] : 0.f;
        float C = (lane < NWARPS) ? s_cnt[buf][lane] : 0.f;
        S = warp_sum16(S);
        C = warp_sum16(C);
        S = __shfl_sync(0xffffffffu, S, 0);   // broadcast lane-0-exact value
        C = __shfl_sync(0xffffffffu, C, 0);

        float ntau = (C >= 0.5f) ? (S - 1.0f) / C : tau;
        if (ntau == tau) break;     // bitwise-identical across all threads -> uniform
        tau = ntau;
        alive = (thread_max > tau);
    }

    // Epilogue: out = max(x - tau, 0), streaming stores.
#pragma unroll
    for (int i = 0; i < VPT; i++) {
        float4 r;
        r.x = fmaxf(v[i].x - tau, 0.f);
        r.y = fmaxf(v[i].y - tau, 0.f);
        r.z = fmaxf(v[i].z - tau, 0.f);
        r.w = fmaxf(v[i].w - tau, 0.f);
        __stcs(&o4[t + i * THREADS], r);
    }
}

extern "C" void kernel_launch(void* const* d_in, const int* in_sizes, int n_in,
                              void* d_out, int out_size) {
    const float* x = (const float*)d_in[0];
    float* out = (float*)d_out;
    sparsemax_kernel<<<ROWS, THREADS>>>(x, out);
}

// round 8
// speedup vs baseline: 2.0991x; 2.0991x over previous
#include <cuda_runtime.h>

#define ROWS 4096
#define COLS 8192
#define THREADS 256
#define NWARPS (THREADS / 32)          // 8
#define VPT (COLS / (THREADS * 4))     // 8 float4 per thread = 32 floats
#define CAP 1024                       // candidate-list capacity (fallback beyond)

__device__ __forceinline__ float warp_sum(float v) {
#pragma unroll
    for (int off = 16; off; off >>= 1)
        v += __shfl_xor_sync(0xffffffffu, v, off);
    return v;
}
__device__ __forceinline__ float warp_max(float v) {
#pragma unroll
    for (int off = 16; off; off >>= 1)
        v = fmaxf(v, __shfl_xor_sync(0xffffffffu, v, off));
    return v;
}

__global__ void __launch_bounds__(THREADS)
sparsemax_kernel(const float* __restrict__ x, float* __restrict__ out) {
    const int row  = blockIdx.x;
    const int t    = threadIdx.x;
    const int warp = t >> 5;
    const int lane = t & 31;

    const float4* __restrict__ x4 = reinterpret_cast<const float4*>(x + (size_t)row * COLS);
    float4*       __restrict__ o4 = reinterpret_cast<float4*>(out + (size_t)row * COLS);

    // Front-batched coalesced loads: 8 x float4 per thread.
    float4 v[VPT];
#pragma unroll
    for (int i = 0; i < VPT; i++) v[i] = x4[t + i * THREADS];

    __shared__ float s_max[NWARPS];
    __shared__ float s_cand[CAP];
    __shared__ int   s_n;
    __shared__ float s_tau;
    __shared__ float s_red[2][NWARPS];   // fallback path only

    // ---- rowmax (one block reduction, one barrier) ----
    float m = v[0].x;
#pragma unroll
    for (int i = 0; i < VPT; i++)
        m = fmaxf(m, fmaxf(fmaxf(v[i].x, v[i].y), fmaxf(v[i].z, v[i].w)));
    m = warp_max(m);
    if (lane == 0) s_max[warp] = m;
    if (t == 0) s_n = 0;
    __syncthreads();
    float rowmax = s_max[0];
#pragma unroll
    for (int w = 1; w < NWARPS; w++) rowmax = fmaxf(rowmax, s_max[w]);   // broadcast LDS

    // ---- candidate scatter: support of sparsemax is a subset of {x > rowmax-1},
    //      since x_max - tau <= sum_support(x - tau) = 1 => tau >= rowmax - 1.
    const float lb = rowmax - 1.0f;
#pragma unroll
    for (int i = 0; i < VPT; i++) {
        float e[4] = {v[i].x, v[i].y, v[i].z, v[i].w};
#pragma unroll
        for (int j = 0; j < 4; j++) {
            if (e[j] > lb) {
                int idx = atomicAdd(&s_n, 1);
                if (idx < CAP) s_cand[idx] = e[j];
            }
        }
    }
    __syncthreads();
    const int n = s_n;

    if (n <= CAP) {
        // ---- warp 0 alone: Newton support-iteration over ~20 candidates.
        //      tau0 = lb has g(tau0) >= 0; iterates increase monotonically and
        //      terminate at the exact sparsemax threshold. No block barriers.
        if (warp == 0) {
            float tau = lb;
#pragma unroll 1
            for (int iter = 0; iter < 32; iter++) {
                float ps = 0.f, pc = 0.f;
                for (int idx = lane; idx < n; idx += 32) {
                    float c = s_cand[idx];
                    if (c > tau) { ps += c; pc += 1.f; }
                }
                float S = warp_sum(ps);
                float C = warp_sum(pc);
                S = __shfl_sync(0xffffffffu, S, 0);
                C = __shfl_sync(0xffffffffu, C, 0);
                float ntau = (C >= 0.5f) ? (S - 1.0f) / C : tau;
                if (ntau == tau) break;
                tau = ntau;
            }
            if (lane == 0) s_tau = tau;
        }
        __syncthreads();
    } else {
        // ---- fallback (adversarial inputs only): block-wide Newton on registers.
        float tau = lb;
#pragma unroll 1
        for (int iter = 0; iter < 32; iter++) {
            float ps = 0.f, pc = 0.f;
#pragma unroll
            for (int i = 0; i < VPT; i++) {
                if (v[i].x > tau) { ps += v[i].x; pc += 1.f; }
                if (v[i].y > tau) { ps += v[i].y; pc += 1.f; }
                if (v[i].z > tau) { ps += v[i].z; pc += 1.f; }
                if (v[i].w > tau) { ps += v[i].w; pc += 1.f; }
            }
            ps = warp_sum(ps);
            pc = warp_sum(pc);
            if (lane == 0) { s_red[0][warp] = ps; s_red[1][warp] = pc; }
            __syncthreads();
            float S = 0.f, C = 0.f;
#pragma unroll
            for (int w = 0; w < NWARPS; w++) { S += s_red[0][w]; C += s_red[1][w]; }
            float ntau = (C >= 0.5f) ? (S - 1.0f) / C : tau;
            __syncthreads();
            if (ntau == tau) break;
            tau = ntau;
        }
        if (t == 0) s_tau = tau;
        __syncthreads();
    }

    const float tau = s_tau;

    // ---- epilogue: out = max(x - tau, 0) ----
#pragma unroll
    for (int i = 0; i < VPT; i++) {
        float4 r;
        r.x = fmaxf(v[i].x - tau, 0.f);
        r.y = fmaxf(v[i].y - tau, 0.f);
        r.z = fmaxf(v[i].z - tau, 0.f);
        r.w = fmaxf(v[i].w - tau, 0.f);
        __stcs(&o4[t + i * THREADS], r);
    }
}

extern "C" void kernel_launch(void* const* d_in, const int* in_sizes, int n_in,
                              void* d_out, int out_size) {
    const float* x = (const float*)d_in[0];
    float* out = (float*)d_out;
    sparsemax_kernel<<<ROWS, THREADS>>>(x, out);
}